// round 1
// baseline (speedup 1.0000x reference)
#include <cuda_runtime.h>
#include <cstdint>
#include <cstdio>

#define E_DIM 1024
#define H_DIM 1024
#define VOC   32000
#define T_STEPS 64
#define NBLK  128          // persistent LSTM blocks (<=148 SMs, 1 block/SM)

// -------- device scratch (no allocs allowed) --------
__device__ float g_X[T_STEPS * E_DIM];     // inputs per step
__device__ float g_hbuf[2 * H_DIM];        // double-buffered hidden state
__device__ float g_hs[T_STEPS * H_DIM];    // all hidden states for fc GEMM
__device__ unsigned int g_cnt;             // monotonic barrier counter

// =====================================================================
// K0: build X (features at t=0, embeddings after), zero h buffers + counter
// =====================================================================
__global__ void prep_kernel(const int* __restrict__ captions,
                            const float* __restrict__ features,
                            const float* __restrict__ etab) {
    int t = blockIdx.x;
    const float* src = (t == 0) ? features : (etab + (size_t)captions[t - 1] * E_DIM);
    for (int k = threadIdx.x; k < E_DIM; k += blockDim.x)
        g_X[t * E_DIM + k] = src[k];
    if (t == 0) {
        for (int k = threadIdx.x; k < 2 * H_DIM; k += blockDim.x) g_hbuf[k] = 0.f;
        if (threadIdx.x == 0) g_cnt = 0u;
    }
}

__device__ __forceinline__ float sigmoidf_(float x) { return 1.f / (1.f + __expf(-x)); }

// =====================================================================
// K1: persistent LSTM. Block b owns h indices [8b, 8b+8).
// Thread mapping: j = tid&7 (local h index), c = tid>>3 (k-chunk, 16 floats).
// W rows (4 gates x 8 j) live in registers: wreg[4][16] per thread.
// Phase A: precompute Xg[t][32 rows] = X[t] @ W_ih^T   (into smem)
// Phase B: 64 steps, global single-phase counter barrier per step.
// =====================================================================
__global__ void __launch_bounds__(512, 1)
lstm_kernel(const float* __restrict__ Wih, const float* __restrict__ Whh,
            const float* __restrict__ bih, const float* __restrict__ bhh) {
    __shared__ float Xg_s[T_STEPS * 32];   // [t][g*8+j]
    __shared__ float partA[16][32];        // [warp][g*8+j]
    __shared__ float gsum_s[32];
    __shared__ float bias_s[32];
    __shared__ float cs[8];

    const int tid = threadIdx.x;
    const int w   = tid >> 5;
    const int l   = tid & 31;
    const int j   = tid & 7;
    const int c   = tid >> 3;     // 0..63
    const int b   = blockIdx.x;
    const int jg  = b * 8 + j;

    if (tid < 32) {
        int g = tid >> 3, jj = tid & 7;
        int row = g * H_DIM + b * 8 + jj;
        bias_s[tid] = bih[row] + bhh[row];
    }
    if (tid < 8) cs[tid] = 0.f;

    float wreg[4][16];

    // ---- load W_ih slice into registers ----
#pragma unroll
    for (int g = 0; g < 4; g++) {
        const float4* p = (const float4*)(Wih + (size_t)(g * H_DIM + jg) * E_DIM + c * 16);
#pragma unroll
        for (int q = 0; q < 4; q++) {
            float4 a = p[q];
            wreg[g][4*q+0] = a.x; wreg[g][4*q+1] = a.y;
            wreg[g][4*q+2] = a.z; wreg[g][4*q+3] = a.w;
        }
    }
    __syncthreads();

    // ---- Phase A: Xg_s[t][g*8+j] = sum_k X[t][k] * W_ih[row][k] ----
    for (int t = 0; t < T_STEPS; t++) {
        float xv[16];
        {
            const float4* xp = (const float4*)(g_X + t * E_DIM + c * 16);
#pragma unroll
            for (int q = 0; q < 4; q++) {
                float4 a = xp[q];
                xv[4*q+0] = a.x; xv[4*q+1] = a.y; xv[4*q+2] = a.z; xv[4*q+3] = a.w;
            }
        }
        float part[4];
#pragma unroll
        for (int g = 0; g < 4; g++) {
            float s = 0.f;
#pragma unroll
            for (int i = 0; i < 16; i++) s = fmaf(wreg[g][i], xv[i], s);
            part[g] = s;
        }
#pragma unroll
        for (int g = 0; g < 4; g++) {
            part[g] += __shfl_xor_sync(0xffffffffu, part[g], 8);
            part[g] += __shfl_xor_sync(0xffffffffu, part[g], 16);
        }
        if (l < 8) {
#pragma unroll
            for (int g = 0; g < 4; g++) partA[w][g * 8 + l] = part[g];
        }
        __syncthreads();
        if (tid < 32) {
            float s = 0.f;
#pragma unroll
            for (int ww = 0; ww < 16; ww++) s += partA[ww][tid];
            Xg_s[t * 32 + tid] = s;
        }
        __syncthreads();
    }

    // ---- swap registers to W_hh slice ----
#pragma unroll
    for (int g = 0; g < 4; g++) {
        const float4* p = (const float4*)(Whh + (size_t)(g * H_DIM + jg) * H_DIM + c * 16);
#pragma unroll
        for (int q = 0; q < 4; q++) {
            float4 a = p[q];
            wreg[g][4*q+0] = a.x; wreg[g][4*q+1] = a.y;
            wreg[g][4*q+2] = a.z; wreg[g][4*q+3] = a.w;
        }
    }
    __syncthreads();

    // ---- Phase B: recurrence ----
    for (int t = 0; t < T_STEPS; t++) {
        const float* hrd = g_hbuf + (t & 1) * H_DIM;
        float hv[16];
        {
            const float4* hp = (const float4*)(hrd + c * 16);
#pragma unroll
            for (int q = 0; q < 4; q++) {
                float4 a = __ldcg(hp + q);   // bypass L1: freshly written by peers
                hv[4*q+0] = a.x; hv[4*q+1] = a.y; hv[4*q+2] = a.z; hv[4*q+3] = a.w;
            }
        }
        float part[4];
#pragma unroll
        for (int g = 0; g < 4; g++) {
            float s = 0.f;
#pragma unroll
            for (int i = 0; i < 16; i++) s = fmaf(wreg[g][i], hv[i], s);
            part[g] = s;
        }
#pragma unroll
        for (int g = 0; g < 4; g++) {
            part[g] += __shfl_xor_sync(0xffffffffu, part[g], 8);
            part[g] += __shfl_xor_sync(0xffffffffu, part[g], 16);
        }
        if (l < 8) {
#pragma unroll
            for (int g = 0; g < 4; g++) partA[w][g * 8 + l] = part[g];
        }
        __syncthreads();
        if (tid < 32) {
            float s = 0.f;
#pragma unroll
            for (int ww = 0; ww < 16; ww++) s += partA[ww][tid];
            gsum_s[tid] = s + Xg_s[t * 32 + tid] + bias_s[tid];
        }
        __syncthreads();
        if (tid < 8) {
            float ii = sigmoidf_(gsum_s[tid]);
            float ff = sigmoidf_(gsum_s[8  + tid]);
            float gg = tanhf    (gsum_s[16 + tid]);
            float oo = sigmoidf_(gsum_s[24 + tid]);
            float cc = ff * cs[tid] + ii * gg;
            cs[tid] = cc;
            float hn = oo * tanhf(cc);
            g_hbuf[((t + 1) & 1) * H_DIM + b * 8 + tid] = hn;   // write NEXT buffer
            g_hs[t * H_DIM + b * 8 + tid] = hn;
        }
        __syncthreads();
        if (tid == 0) {
            __threadfence();                 // release h writes to L2
            atomicAdd(&g_cnt, 1u);
            unsigned int target = (unsigned)NBLK * (unsigned)(t + 1);
            unsigned int v;
            do {
                asm volatile("ld.acquire.gpu.u32 %0, [%1];"
                             : "=r"(v) : "l"(&g_cnt) : "memory");
            } while (v < target);
        }
        __syncthreads();
    }
}

// =====================================================================
// K2: logits[64][32000] = hs @ fc_W^T + fc_b   (fp32, packed f32x2 FMA)
// Tile: V=128 per block (250 blocks), T=64, K-chunks of 32.
// 128 threads: vg = tid&15, tg = tid>>4. Thread owns 8 v (stride 16) x 8 t.
// =====================================================================
#define VT 128
#define KC 32
#define SWP (VT + 1)   // w_s row pad -> conflict-free compute loads
#define SHP 66         // hs_s row pad (even, for 8B-aligned float2)

__device__ __forceinline__ unsigned long long pack2(float x, float y) {
    unsigned long long r;
    asm("mov.b64 %0, {%1, %2};" : "=l"(r) : "f"(x), "f"(y));
    return r;
}
__device__ __forceinline__ void fma2(unsigned long long& d,
                                     unsigned long long a, unsigned long long b) {
    asm("fma.rn.f32x2 %0, %1, %2, %0;" : "+l"(d) : "l"(a), "l"(b));
}
__device__ __forceinline__ float2 unpack2(unsigned long long v) {
    float2 r;
    asm("mov.b64 {%0, %1}, %2;" : "=f"(r.x), "=f"(r.y) : "l"(v));
    return r;
}

__global__ void __launch_bounds__(128, 2)
fc_kernel(const float* __restrict__ fcW, const float* __restrict__ fcb,
          float* __restrict__ out) {
    __shared__ __align__(16) float w_s[KC][SWP];   // [k][v]
    __shared__ __align__(16) float hs_s[KC][SHP];  // [k][t]

    const int tid = threadIdx.x;
    const int vg  = tid & 15;
    const int tg  = tid >> 4;           // 0..7
    const int vbase = blockIdx.x * VT;

    unsigned long long acc[8][4];       // [vi][t-pair], lanes = (t0, t0+1)
#pragma unroll
    for (int vi = 0; vi < 8; vi++)
#pragma unroll
        for (int p = 0; p < 4; p++) acc[vi][p] = 0ull;

    for (int kb = 0; kb < E_DIM; kb += KC) {
        // load W tile: w_s[k][v] = fcW[vbase+v][kb+k]  (float4 along k)
        for (int q = tid; q < VT * (KC / 4); q += 128) {
            int v  = q >> 3;            // KC/4 = 8
            int k4 = q & 7;
            float4 a = *(const float4*)(fcW + (size_t)(vbase + v) * E_DIM + kb + k4 * 4);
            w_s[4*k4+0][v] = a.x; w_s[4*k4+1][v] = a.y;
            w_s[4*k4+2][v] = a.z; w_s[4*k4+3][v] = a.w;
        }
        // load hs tile: hs_s[k][t] = g_hs[t][kb+k]
        for (int q = tid; q < T_STEPS * (KC / 4); q += 128) {
            int t  = q >> 3;
            int k4 = q & 7;
            float4 a = *(const float4*)(g_hs + t * H_DIM + kb + k4 * 4);
            hs_s[4*k4+0][t] = a.x; hs_s[4*k4+1][t] = a.y;
            hs_s[4*k4+2][t] = a.z; hs_s[4*k4+3][t] = a.w;
        }
        __syncthreads();

#pragma unroll 8
        for (int k = 0; k < KC; k++) {
            unsigned long long wp[8];
#pragma unroll
            for (int vi = 0; vi < 8; vi++) {
                float wv = w_s[k][vi * 16 + vg];
                wp[vi] = pack2(wv, wv);
            }
            unsigned long long hp[4];
#pragma unroll
            for (int p = 0; p < 4; p++)
                hp[p] = *(const unsigned long long*)&hs_s[k][tg * 8 + 2 * p];
#pragma unroll
            for (int vi = 0; vi < 8; vi++)
#pragma unroll
                for (int p = 0; p < 4; p++)
                    fma2(acc[vi][p], wp[vi], hp[p]);
        }
        __syncthreads();
    }

    // epilogue: + bias, scatter to out[t][v]
#pragma unroll
    for (int vi = 0; vi < 8; vi++) {
        int v = vbase + vi * 16 + vg;
        float bv = fcb[v];
#pragma unroll
        for (int p = 0; p < 4; p++) {
            float2 a = unpack2(acc[vi][p]);
            int t0 = tg * 8 + 2 * p;
            out[(size_t)t0 * VOC + v]       = a.x + bv;
            out[(size_t)(t0 + 1) * VOC + v] = a.y + bv;
        }
    }
}

// =====================================================================
// launch
// =====================================================================
extern "C" void kernel_launch(void* const* d_in, const int* in_sizes, int n_in,
                              void* d_out, int out_size) {
    const int*   captions = (const int*)  d_in[0];
    const float* features = (const float*)d_in[1];
    const float* etab     = (const float*)d_in[2];
    const float* W_ih     = (const float*)d_in[3];
    const float* W_hh     = (const float*)d_in[4];
    const float* b_ih     = (const float*)d_in[5];
    const float* b_hh     = (const float*)d_in[6];
    const float* fc_W     = (const float*)d_in[7];
    const float* fc_b     = (const float*)d_in[8];
    float* out = (float*)d_out;

    prep_kernel<<<T_STEPS, 256>>>(captions, features, etab);
    lstm_kernel<<<NBLK, 512>>>(W_ih, W_hh, b_ih, b_hh);
    fc_kernel<<<VOC / VT, 128>>>(fc_W, fc_b, out);
}

// round 3
// speedup vs baseline: 1.3618x; 1.3618x over previous
#include <cuda_runtime.h>
#include <cuda_bf16.h>
#include <cstdint>
#include <cstdio>

#define E_DIM 1024
#define H_DIM 1024
#define VOC   32000
#define T_STEPS 64
#define NBLK  128          // persistent LSTM blocks

// -------- device scratch (no allocs allowed) --------
__device__ float g_X[T_STEPS * E_DIM];     // inputs per step
__device__ float g_hbuf[2 * H_DIM];        // double-buffered hidden state
__device__ float g_hs[T_STEPS * H_DIM];    // all hidden states for fc GEMM
__device__ unsigned int g_cnt;             // monotonic barrier counter

// =====================================================================
// K0: build X (features at t=0, embeddings after), zero h buffers + counter
// =====================================================================
__global__ void prep_kernel(const int* __restrict__ captions,
                            const float* __restrict__ features,
                            const float* __restrict__ etab) {
    int t = blockIdx.x;
    const float* src = (t == 0) ? features : (etab + (size_t)captions[t - 1] * E_DIM);
    for (int k = threadIdx.x; k < E_DIM; k += blockDim.x)
        g_X[t * E_DIM + k] = src[k];
    if (t == 0) {
        for (int k = threadIdx.x; k < 2 * H_DIM; k += blockDim.x) g_hbuf[k] = 0.f;
        if (threadIdx.x == 0) g_cnt = 0u;
    }
}

__device__ __forceinline__ float sigmoidf_(float x) { return 1.f / (1.f + __expf(-x)); }

// =====================================================================
// K1: persistent LSTM (known-good from round 1).
// =====================================================================
__global__ void __launch_bounds__(512, 1)
lstm_kernel(const float* __restrict__ Wih, const float* __restrict__ Whh,
            const float* __restrict__ bih, const float* __restrict__ bhh) {
    __shared__ float Xg_s[T_STEPS * 32];   // [t][g*8+j]
    __shared__ float partA[16][32];        // [warp][g*8+j]
    __shared__ float gsum_s[32];
    __shared__ float bias_s[32];
    __shared__ float cs[8];

    const int tid = threadIdx.x;
    const int w   = tid >> 5;
    const int l   = tid & 31;
    const int j   = tid & 7;
    const int c   = tid >> 3;     // 0..63
    const int b   = blockIdx.x;
    const int jg  = b * 8 + j;

    if (tid < 32) {
        int g = tid >> 3, jj = tid & 7;
        int row = g * H_DIM + b * 8 + jj;
        bias_s[tid] = bih[row] + bhh[row];
    }
    if (tid < 8) cs[tid] = 0.f;

    float wreg[4][16];

#pragma unroll
    for (int g = 0; g < 4; g++) {
        const float4* p = (const float4*)(Wih + (size_t)(g * H_DIM + jg) * E_DIM + c * 16);
#pragma unroll
        for (int q = 0; q < 4; q++) {
            float4 a = p[q];
            wreg[g][4*q+0] = a.x; wreg[g][4*q+1] = a.y;
            wreg[g][4*q+2] = a.z; wreg[g][4*q+3] = a.w;
        }
    }
    __syncthreads();

    for (int t = 0; t < T_STEPS; t++) {
        float xv[16];
        {
            const float4* xp = (const float4*)(g_X + t * E_DIM + c * 16);
#pragma unroll
            for (int q = 0; q < 4; q++) {
                float4 a = xp[q];
                xv[4*q+0] = a.x; xv[4*q+1] = a.y; xv[4*q+2] = a.z; xv[4*q+3] = a.w;
            }
        }
        float part[4];
#pragma unroll
        for (int g = 0; g < 4; g++) {
            float s = 0.f;
#pragma unroll
            for (int i = 0; i < 16; i++) s = fmaf(wreg[g][i], xv[i], s);
            part[g] = s;
        }
#pragma unroll
        for (int g = 0; g < 4; g++) {
            part[g] += __shfl_xor_sync(0xffffffffu, part[g], 8);
            part[g] += __shfl_xor_sync(0xffffffffu, part[g], 16);
        }
        if (l < 8) {
#pragma unroll
            for (int g = 0; g < 4; g++) partA[w][g * 8 + l] = part[g];
        }
        __syncthreads();
        if (tid < 32) {
            float s = 0.f;
#pragma unroll
            for (int ww = 0; ww < 16; ww++) s += partA[ww][tid];
            Xg_s[t * 32 + tid] = s;
        }
        __syncthreads();
    }

#pragma unroll
    for (int g = 0; g < 4; g++) {
        const float4* p = (const float4*)(Whh + (size_t)(g * H_DIM + jg) * H_DIM + c * 16);
#pragma unroll
        for (int q = 0; q < 4; q++) {
            float4 a = p[q];
            wreg[g][4*q+0] = a.x; wreg[g][4*q+1] = a.y;
            wreg[g][4*q+2] = a.z; wreg[g][4*q+3] = a.w;
        }
    }
    __syncthreads();

    for (int t = 0; t < T_STEPS; t++) {
        const float* hrd = g_hbuf + (t & 1) * H_DIM;
        float hv[16];
        {
            const float4* hp = (const float4*)(hrd + c * 16);
#pragma unroll
            for (int q = 0; q < 4; q++) {
                float4 a = __ldcg(hp + q);
                hv[4*q+0] = a.x; hv[4*q+1] = a.y; hv[4*q+2] = a.z; hv[4*q+3] = a.w;
            }
        }
        float part[4];
#pragma unroll
        for (int g = 0; g < 4; g++) {
            float s = 0.f;
#pragma unroll
            for (int i = 0; i < 16; i++) s = fmaf(wreg[g][i], hv[i], s);
            part[g] = s;
        }
#pragma unroll
        for (int g = 0; g < 4; g++) {
            part[g] += __shfl_xor_sync(0xffffffffu, part[g], 8);
            part[g] += __shfl_xor_sync(0xffffffffu, part[g], 16);
        }
        if (l < 8) {
#pragma unroll
            for (int g = 0; g < 4; g++) partA[w][g * 8 + l] = part[g];
        }
        __syncthreads();
        if (tid < 32) {
            float s = 0.f;
#pragma unroll
            for (int ww = 0; ww < 16; ww++) s += partA[ww][tid];
            gsum_s[tid] = s + Xg_s[t * 32 + tid] + bias_s[tid];
        }
        __syncthreads();
        if (tid < 8) {
            float ii = sigmoidf_(gsum_s[tid]);
            float ff = sigmoidf_(gsum_s[8  + tid]);
            float gg = tanhf    (gsum_s[16 + tid]);
            float oo = sigmoidf_(gsum_s[24 + tid]);
            float cc = ff * cs[tid] + ii * gg;
            cs[tid] = cc;
            float hn = oo * tanhf(cc);
            g_hbuf[((t + 1) & 1) * H_DIM + b * 8 + tid] = hn;
            g_hs[t * H_DIM + b * 8 + tid] = hn;
        }
        __syncthreads();
        if (tid == 0) {
            __threadfence();
            atomicAdd(&g_cnt, 1u);
            unsigned int target = (unsigned)NBLK * (unsigned)(t + 1);
            unsigned int v;
            do {
                asm volatile("ld.acquire.gpu.u32 %0, [%1];"
                             : "=r"(v) : "l"(&g_cnt) : "memory");
            } while (v < target);
        }
        __syncthreads();
    }
}

// =====================================================================
// K2: fc GEMM via mma.sync m16n8k16 bf16, 2-way split (3 passes):
//   C = Ahi*Bhi + Alo*Bhi + Ahi*Blo     (~1e-5 rel accuracy)
// Per CTA: M=128 vocab rows, N=64 timesteps, K=1024 in chunks of 64.
// A, B tiles stored row-major [row][k] as bf16, 128B rows, SW128 swizzle.
// Plain ldmatrix.x4 yields both A (m16k16) and B (k16n8) fragments.
// =====================================================================
#define FC_M    128
#define FC_KC   64                  // fp32 elems per K-chunk (=128B bf16 row)
#define FC_NCH  (E_DIM / FC_KC)     // 16 chunks

#define SWZ(x) ((x) ^ (((x) >> 3) & 0x70))

__device__ __forceinline__ uint32_t smem_u32(const void* p) {
    uint32_t a;
    asm("{ .reg .u64 t; cvta.to.shared.u64 t, %1; cvt.u32.u64 %0, t; }" : "=r"(a) : "l"(p));
    return a;
}

// split float4 -> bf16x2 hi pair + lo pair (Dekker: lo = bf16(x - f32(hi)))
__device__ __forceinline__ void split4(float4 a, uint2& hi, uint2& lo) {
    __nv_bfloat162 h0 = __float22bfloat162_rn(make_float2(a.x, a.y));
    __nv_bfloat162 h1 = __float22bfloat162_rn(make_float2(a.z, a.w));
    float2 f0 = __bfloat1622float2(h0);
    float2 f1 = __bfloat1622float2(h1);
    __nv_bfloat162 l0 = __float22bfloat162_rn(make_float2(a.x - f0.x, a.y - f0.y));
    __nv_bfloat162 l1 = __float22bfloat162_rn(make_float2(a.z - f1.x, a.w - f1.y));
    hi.x = *reinterpret_cast<uint32_t*>(&h0);
    hi.y = *reinterpret_cast<uint32_t*>(&h1);
    lo.x = *reinterpret_cast<uint32_t*>(&l0);
    lo.y = *reinterpret_cast<uint32_t*>(&l1);
}

#define LDM_X4(r, a)                                                          \
    asm volatile("ldmatrix.sync.aligned.m8n8.x4.shared.b16 {%0,%1,%2,%3}, [%4];" \
        : "=r"((r)[0]), "=r"((r)[1]), "=r"((r)[2]), "=r"((r)[3]) : "r"(a))

#define MMA16816(d, a, b0, b1)                                                \
    asm volatile("mma.sync.aligned.m16n8k16.row.col.f32.bf16.bf16.f32 "       \
        "{%0,%1,%2,%3},{%4,%5,%6,%7},{%8,%9},{%0,%1,%2,%3};"                  \
        : "+f"((d)[0]), "+f"((d)[1]), "+f"((d)[2]), "+f"((d)[3])              \
        : "r"((a)[0]), "r"((a)[1]), "r"((a)[2]), "r"((a)[3]),                 \
          "r"(b0), "r"(b1))

__global__ void __launch_bounds__(128, 2)
fc_mma_kernel(const float* __restrict__ fcW, const float* __restrict__ fcb,
              float* __restrict__ out) {
    // 48KB static smem exactly
    __shared__ __align__(16) char As_hi[FC_M * 128];      // 16KB
    __shared__ __align__(16) char As_lo[FC_M * 128];      // 16KB
    __shared__ __align__(16) char Bs_hi[T_STEPS * 128];   // 8KB
    __shared__ __align__(16) char Bs_lo[T_STEPS * 128];   // 8KB

    const int tid  = threadIdx.x;
    const int wid  = tid >> 5;
    const int lane = tid & 31;
    const int vbase = blockIdx.x * FC_M;
    const int m0 = wid * 32;                 // warp's M-strip

    const uint32_t sAhi = smem_u32(As_hi), sAlo = smem_u32(As_lo);
    const uint32_t sBhi = smem_u32(Bs_hi), sBlo = smem_u32(Bs_lo);

    // per-lane ldmatrix address pieces
    // A: row = m0 + (lane&15), k-half = (lane>>4)*16
    const int a_row  = m0 + (lane & 15);
    const uint32_t a_roff = (uint32_t)a_row * 128;
    const uint32_t a_xor  = (uint32_t)(a_row & 7) << 4;
    const uint32_t a_kh   = (uint32_t)(lane >> 4) * 16;
    // B: row n = n0 + (lane&7) + ((lane>>4)&1)*8, k-half = ((lane>>3)&1)*16
    const int b_rsub = (lane & 7) + ((lane >> 4) & 1) * 8;
    const uint32_t b_xor = (uint32_t)(lane & 7) << 4;
    const uint32_t b_kh  = (uint32_t)((lane >> 3) & 1) * 16;

    float acc[2][8][4];
#pragma unroll
    for (int mt = 0; mt < 2; mt++)
#pragma unroll
        for (int nt = 0; nt < 8; nt++)
#pragma unroll
            for (int q = 0; q < 4; q++) acc[mt][nt][q] = 0.f;

    for (int c = 0; c < FC_NCH; c++) {
        __syncthreads();    // previous mma reads done
        // ---- stage A: 128 rows x 64 fp32 -> bf16 hi/lo ----
#pragma unroll
        for (int p = 0; p < 16; p++) {
            int idx = tid + p * 128;         // 0..2047
            int row = idx >> 4, f4 = idx & 15;
            float4 a = *(const float4*)(fcW + (size_t)(vbase + row) * E_DIM
                                        + c * FC_KC + f4 * 4);
            uint2 hi, lo; split4(a, hi, lo);
            uint32_t off = SWZ((uint32_t)(row * 128 + f4 * 8));
            *(uint2*)(As_hi + off) = hi;
            *(uint2*)(As_lo + off) = lo;
        }
        // ---- stage B: 64 rows x 64 fp32 from g_hs ----
#pragma unroll
        for (int p = 0; p < 8; p++) {
            int idx = tid + p * 128;         // 0..1023
            int row = idx >> 4, f4 = idx & 15;
            float4 a = *(const float4*)(g_hs + row * H_DIM + c * FC_KC + f4 * 4);
            uint2 hi, lo; split4(a, hi, lo);
            uint32_t off = SWZ((uint32_t)(row * 128 + f4 * 8));
            *(uint2*)(Bs_hi + off) = hi;
            *(uint2*)(Bs_lo + off) = lo;
        }
        __syncthreads();

        // ---- mma over 4 k16-steps ----
#pragma unroll
        for (int ks = 0; ks < 4; ks++) {
            const uint32_t akb = (uint32_t)(ks * 32) + a_kh;
            const uint32_t bkb = (uint32_t)(ks * 32) + b_kh;

            uint32_t ah[2][4], al[2][4];
#pragma unroll
            for (int mt = 0; mt < 2; mt++) {
                uint32_t off = a_roff + (uint32_t)(mt * 16 * 128) + (akb ^ a_xor);
                LDM_X4(ah[mt], sAhi + off);
                LDM_X4(al[mt], sAlo + off);
            }
            uint32_t bh[4][4], bl[4][4];
#pragma unroll
            for (int bp = 0; bp < 4; bp++) {
                uint32_t n = (uint32_t)(bp * 16 + b_rsub);
                uint32_t off = n * 128 + (bkb ^ b_xor);
                LDM_X4(bh[bp], sBhi + off);
                LDM_X4(bl[bp], sBlo + off);
            }
#pragma unroll
            for (int mt = 0; mt < 2; mt++)
#pragma unroll
                for (int nt = 0; nt < 8; nt++) {
                    const int bp = nt >> 1, sel = (nt & 1) * 2;
                    MMA16816(acc[mt][nt], ah[mt], bh[bp][sel], bh[bp][sel + 1]);
                    MMA16816(acc[mt][nt], al[mt], bh[bp][sel], bh[bp][sel + 1]);
                    MMA16816(acc[mt][nt], ah[mt], bl[bp][sel], bl[bp][sel + 1]);
                }
        }
    }

    // ---- epilogue: C[m][n] -> out[n*VOC + vbase+m] + bias ----
    const int g  = lane >> 2;
    const int t4 = lane & 3;
#pragma unroll
    for (int mt = 0; mt < 2; mt++) {
        int v0 = vbase + m0 + mt * 16 + g;
        float bv0 = fcb[v0];
        float bv8 = fcb[v0 + 8];
#pragma unroll
        for (int nt = 0; nt < 8; nt++) {
            int t0 = nt * 8 + t4 * 2;
            out[(size_t)t0 * VOC + v0]           = acc[mt][nt][0] + bv0;
            out[(size_t)(t0 + 1) * VOC + v0]     = acc[mt][nt][1] + bv0;
            out[(size_t)t0 * VOC + v0 + 8]       = acc[mt][nt][2] + bv8;
            out[(size_t)(t0 + 1) * VOC + v0 + 8] = acc[mt][nt][3] + bv8;
        }
    }
}

// =====================================================================
// launch
// =====================================================================
extern "C" void kernel_launch(void* const* d_in, const int* in_sizes, int n_in,
                              void* d_out, int out_size) {
    const int*   captions = (const int*)  d_in[0];
    const float* features = (const float*)d_in[1];
    const float* etab     = (const float*)d_in[2];
    const float* W_ih     = (const float*)d_in[3];
    const float* W_hh     = (const float*)d_in[4];
    const float* b_ih     = (const float*)d_in[5];
    const float* b_hh     = (const float*)d_in[6];
    const float* fc_W     = (const float*)d_in[7];
    const float* fc_b     = (const float*)d_in[8];
    float* out = (float*)d_out;

    prep_kernel<<<T_STEPS, 256>>>(captions, features, etab);
    lstm_kernel<<<NBLK, 512>>>(W_ih, W_hh, b_ih, b_hh);
    fc_mma_kernel<<<VOC / FC_M, 128>>>(fc_W, fc_b, out);
}